// round 15
// baseline (speedup 1.0000x reference)
#include <cuda_runtime.h>
#include <cuda_bf16.h>
#include <math.h>
#include <stdint.h>

#define NB 16
#define NT 32
#define HH 40
#define WW 40
#define FF 40

typedef __nv_bfloat16 bf16;

// ---------------- scratch (no allocations allowed) ----------------
__device__ float g_seqA[(size_t)NB*NT*HH*WW*FF];      // 131 MB (layer-3 fp32 out)
__device__ float g_zx [(size_t)NB*NT*HH*WW*160];      // 524 MB x-conv precompute
__device__ bf16  g_sqh[(size_t)NB*NT*HH*WW*FF];       // inter-layer out split hi
__device__ bf16  g_sql[(size_t)NB*NT*HH*WW*FF];       // inter-layer out split lo
__device__ bf16  g_hA2[2*(size_t)NB*HH*WW*FF];        // h ping: [hi | lo]
__device__ bf16  g_hB2[2*(size_t)NB*HH*WW*FF];        // h pong: [hi | lo]
__device__ float g_c  [NB*HH*WW*FF];
// B pack: chunk0 = pos8 [160][48]; chunks1..4 = pos{2c-2,2c-1} [160][80] each
#define BPK (160*48 + 4*160*80)                        // 58880
__device__ bf16 g_Bxh[BPK], g_Bxl[BPK];
__device__ bf16 g_Bhh[BPK], g_Bhl[BPK];

__global__ void zero_kernel(float* __restrict__ p, int n) {
    int i = blockIdx.x * blockDim.x + threadIdx.x;
    if (i < n) p[i] = 0.f;
}

__device__ __forceinline__ float hsig(float x) {
    return fminf(fmaxf(0.2f * x + 0.5f, 0.f), 1.f);
}
__device__ __forceinline__ void mma16(float* d, const uint32_t* a, uint32_t b0, uint32_t b1) {
    asm volatile("mma.sync.aligned.m16n8k16.row.col.f32.bf16.bf16.f32 "
        "{%0,%1,%2,%3}, {%4,%5,%6,%7}, {%8,%9}, {%0,%1,%2,%3};"
        : "+f"(d[0]), "+f"(d[1]), "+f"(d[2]), "+f"(d[3])
        : "r"(a[0]), "r"(a[1]), "r"(a[2]), "r"(a[3]), "r"(b0), "r"(b1));
}
__device__ __forceinline__ void split_bf16(float v, bf16& hi, bf16& lo) {
    hi = __float2bfloat16_rn(v);
    lo = __float2bfloat16_rn(v - __bfloat162float(hi));
}
// split float2 -> two packed bf16x2 words (hi word, lo word)
__device__ __forceinline__ void split2(float2 v, uint32_t& hw, uint32_t& lw) {
    __nv_bfloat162 H, L;
    split_bf16(v.x, H.x, L.x);
    split_bf16(v.y, H.y, L.y);
    hw = *(uint32_t*)&H;
    lw = *(uint32_t*)&L;
}

// ---- weight prepass ----
// mode 0 (CIN=1):  [n][16]: k<9 -> W[k*160+n], else 0           (160*16)
// mode 1 (CIN=40): chunk-packed (see BPK comment)               (58880)
__global__ void build_B_kernel(const float* __restrict__ W, int mode,
                               bf16* __restrict__ Bh, bf16* __restrict__ Bl)
{
    int idx = blockIdx.x * blockDim.x + threadIdx.x;
    float v = 0.f;
    if (mode == 0) {
        if (idx >= 160 * 16) return;
        int n = idx / 16, k = idx & 15;
        if (k < 9) v = W[k * 160 + n];
    } else {
        if (idx >= BPK) return;
        if (idx < 160 * 48) {
            int n = idx / 48, j = idx % 48;
            if (j < 40) v = W[(size_t)(8 * 40 + j) * 160 + n];
        } else {
            int r = idx - 160 * 48;
            int c1 = r / 12800, rr = r - c1 * 12800;
            int n = rr / 80, j = rr - n * 80;
            int pos = 2 * c1 + j / 40, ch = j - (j / 40) * 40;
            v = W[(size_t)(pos * 40 + ch) * 160 + n];
        }
    }
    bf16 hi, lo;
    split_bf16(v, hi, lo);
    Bh[idx] = hi;
    Bl[idx] = lo;
}

// ---------------- GEMM step via mma.sync bf16 (3-term hi/lo split) --------
// z[M,160] = im2col(X)[M, K=9*CIN] @ B[160,K]^T
// CIN=40: 5 chunks (1x48k + 4x80k = 23 ksteps), B staged in two n-halves.
// MODE 0: PRE (store z fp32).  MODE 1: REC, split-bf16 out.  MODE 2: REC, fp32 out.
template<int CIN, int MODE>
__global__ __launch_bounds__(128, 3)
void mma_step(const float* __restrict__ Xf,                 // CIN=1 source (fp32)
              const bf16* __restrict__ Xh, const bf16* __restrict__ Xl,  // CIN=40 source
              long long xbs,
              const bf16* __restrict__ Bh_g, const bf16* __restrict__ Bl_g,
              float* __restrict__ zpre,
              const float* __restrict__ zx_t, long long zbs,
              const float* __restrict__ bias,
              const float* __restrict__ gam, const float* __restrict__ bet,
              const float* __restrict__ mu, const float* __restrict__ var,
              bf16* __restrict__ hh_next, bf16* __restrict__ hl_next,
              float* __restrict__ c_buf,
              float* __restrict__ out_f,
              bf16* __restrict__ out_h, bf16* __restrict__ out_l,
              long long bso)
{
    constexpr int ASTR = (CIN == 1) ? 24 : 88;     // bf16 row stride
    constexpr int AS2  = ASTR / 2;                 // b32 row stride
    constexpr int BROWS = (CIN == 1) ? 160 : 80;   // B buffer rows

    extern __shared__ char smem[];
    bf16* sAh = (bf16*)smem;
    bf16* sAl = sAh + 64 * ASTR;
    bf16* sBh = sAl + 64 * ASTR;
    bf16* sBl = sBh + BROWS * ASTR;
    float* sPar = (float*)(sBl + BROWS * ASTR);    // bias[160], scale[40], shift[40]

    const int tid = threadIdx.x;
    const int w   = tid >> 5;
    const int lane = tid & 31;
    const int gid = lane >> 2;
    const int tig = lane & 3;
    const int p0  = blockIdx.x * 64;

    if (MODE != 0) {
        for (int i = tid; i < 240; i += 128) {
            if (i < 160) sPar[i] = bias[i];
            else if (i < 200) {
                int f = i - 160;
                sPar[i] = gam[f] * rsqrtf(var[f] + 1e-3f);
            } else {
                int f = i - 200;
                sPar[i] = bet[f] - mu[f] * (gam[f] * rsqrtf(var[f] + 1e-3f));
            }
        }
    }

    float d[20][4];
#pragma unroll
    for (int j = 0; j < 20; j++)
#pragma unroll
        for (int e = 0; e < 4; e++) d[j][e] = 0.f;

    if (CIN == 1) {
        // ---------------- layer-0 PRE path (K=9 -> 16) ----------------
        for (int i = tid; i < 64; i += 128) {
            int p = p0 + i;
            int unit = p / 1600, pp = p - unit * 1600;
            int pr = pp / 40, pw = pp - pr * 40;
            bf16* ph = sAh + i * ASTR;
            bf16* pl = sAl + i * ASTR;
#pragma unroll
            for (int k = 0; k < 16; k += 2) {
                float v0 = 0.f, v1 = 0.f;
                if (k < 9) {
                    int rr = pr + k / 3 - 1, cc = pw + k % 3 - 1;
                    if ((unsigned)rr < 40u && (unsigned)cc < 40u)
                        v0 = Xf[(size_t)unit * xbs + rr * 40 + cc];
                }
                if (k + 1 < 9) {
                    int k1 = k + 1;
                    int rr = pr + k1 / 3 - 1, cc = pw + k1 % 3 - 1;
                    if ((unsigned)rr < 40u && (unsigned)cc < 40u)
                        v1 = Xf[(size_t)unit * xbs + rr * 40 + cc];
                }
                __nv_bfloat162 h2, l2;
                split_bf16(v0, h2.x, l2.x);
                split_bf16(v1, h2.y, l2.y);
                *(__nv_bfloat162*)(ph + k) = h2;
                *(__nv_bfloat162*)(pl + k) = l2;
            }
        }
        for (int i = tid; i < 320; i += 128) {
            int n = i >> 1, g = i & 1;
            *(float4*)(sBh + n * ASTR + g * 8) = *(const float4*)(Bh_g + n * 16 + g * 8);
            *(float4*)(sBl + n * ASTR + g * 8) = *(const float4*)(Bl_g + n * 16 + g * 8);
        }
        __syncthreads();

        const uint32_t* Ah32 = (const uint32_t*)sAh;
        const uint32_t* Al32 = (const uint32_t*)sAl;
        const uint32_t* Bh32 = (const uint32_t*)sBh;
        const uint32_t* Bl32 = (const uint32_t*)sBl;
        uint32_t ah[4], al[4];
        {
            int ra = (w * 16 + gid) * AS2 + tig;
            ah[0] = Ah32[ra];      ah[1] = Ah32[ra + 8 * AS2];
            ah[2] = Ah32[ra + 4];  ah[3] = Ah32[ra + 8 * AS2 + 4];
            al[0] = Al32[ra];      al[1] = Al32[ra + 8 * AS2];
            al[2] = Al32[ra + 4];  al[3] = Al32[ra + 8 * AS2 + 4];
        }
#pragma unroll
        for (int j = 0; j < 20; j++) {
            int rb = (8 * j + gid) * AS2 + tig;
            uint32_t bh0 = Bh32[rb], bh1 = Bh32[rb + 4];
            uint32_t bl0 = Bl32[rb], bl1 = Bl32[rb + 4];
            mma16(d[j], ah, bh0, bh1);
            mma16(d[j], ah, bl0, bl1);
            mma16(d[j], al, bh0, bh1);
        }
        __syncthreads();
    } else {
        // ---------------- CIN=40: 5 chunks, B in n-halves ----------------
        // pre-zero A pad cols 40..47 (used by chunk 0 only, which runs first)
        for (int r = tid; r < 64; r += 128) {
            *(float4*)(sAh + r * ASTR + 40) = make_float4(0.f, 0.f, 0.f, 0.f);
            *(float4*)(sAl + r * ASTR + 40) = make_float4(0.f, 0.f, 0.f, 0.f);
        }

#pragma unroll 1
        for (int c = 0; c < 5; c++) {
            const int KS = c ? 5 : 3;
#pragma unroll 1
            for (int h = 0; h < 2; h++) {
                if (h == 0) {
                    // ---- stage A(c): gather pre-split bf16 pairs (16B units)
                    if (c == 0) {
                        // single position: pos 8 (dy=+1, dx=+1), cols 0..39
                        for (int i = tid; i < 320; i += 128) {
                            int row = i / 5, slot = i % 5;
                            int p = p0 + row;
                            int unit = p / 1600, pp = p - unit * 1600;
                            int pr = pp / 40, pw = pp - pr * 40;
                            int rr = pr + 1, cc = pw + 1;
                            uint4 vh = make_uint4(0, 0, 0, 0), vl = vh;
                            if (rr < 40 && cc < 40) {
                                size_t src = (size_t)unit * xbs + (size_t)(rr * 40 + cc) * 40 + slot * 8;
                                vh = *(const uint4*)(Xh + src);
                                vl = *(const uint4*)(Xl + src);
                            }
                            *(uint4*)(sAh + row * ASTR + slot * 8) = vh;
                            *(uint4*)(sAl + row * ASTR + slot * 8) = vl;
                        }
                    } else {
                        // pair chunk: positions 2(c-1), 2(c-1)+1 -> cols 0..79
                        const int pb = 2 * (c - 1);
                        for (int i = tid; i < 640; i += 128) {
                            int row = i / 10, q = i - row * 10;
                            int posl = q / 5, slot = q - posl * 5;
                            int pos = pb + posl;
                            int p = p0 + row;
                            int unit = p / 1600, pp = p - unit * 1600;
                            int pr = pp / 40, pw = pp - pr * 40;
                            int rr = pr + pos / 3 - 1, cc = pw + pos % 3 - 1;
                            uint4 vh = make_uint4(0, 0, 0, 0), vl = vh;
                            if ((unsigned)rr < 40u && (unsigned)cc < 40u) {
                                size_t src = (size_t)unit * xbs + (size_t)(rr * 40 + cc) * 40 + slot * 8;
                                vh = *(const uint4*)(Xh + src);
                                vl = *(const uint4*)(Xl + src);
                            }
                            int col = posl * 40 + slot * 8;
                            *(uint4*)(sAh + row * ASTR + col) = vh;
                            *(uint4*)(sAl + row * ASTR + col) = vl;
                        }
                    }
                }
                // ---- stage B n-half h
                if (c == 0) {
                    for (int i = tid; i < 480; i += 128) {
                        int nl = i / 6, s = i - (i / 6) * 6;
                        size_t src = (size_t)(80 * h + nl) * 48 + s * 8;
                        *(uint4*)(sBh + nl * ASTR + s * 8) = *(const uint4*)(Bh_g + src);
                        *(uint4*)(sBl + nl * ASTR + s * 8) = *(const uint4*)(Bl_g + src);
                    }
                } else {
                    const size_t cb = 160 * 48 + (size_t)(c - 1) * 12800;
                    for (int i = tid; i < 800; i += 128) {
                        int nl = i / 10, s = i - (i / 10) * 10;
                        size_t src = cb + (size_t)(80 * h + nl) * 80 + s * 8;
                        *(uint4*)(sBh + nl * ASTR + s * 8) = *(const uint4*)(Bh_g + src);
                        *(uint4*)(sBl + nl * ASTR + s * 8) = *(const uint4*)(Bl_g + src);
                    }
                }
                __syncthreads();

                // ---- mma: ksteps x (10 local j) x 3 terms
                const uint32_t* Ah32 = (const uint32_t*)sAh;
                const uint32_t* Al32 = (const uint32_t*)sAl;
                const uint32_t* Bh32 = (const uint32_t*)sBh;
                const uint32_t* Bl32 = (const uint32_t*)sBl;
#pragma unroll
                for (int ks = 0; ks < 5; ks++) {
                    if (ks >= KS) break;
                    uint32_t ah[4], al[4];
                    int ra = (w * 16 + gid) * AS2 + ks * 8 + tig;
                    ah[0] = Ah32[ra];      ah[1] = Ah32[ra + 8 * AS2];
                    ah[2] = Ah32[ra + 4];  ah[3] = Ah32[ra + 8 * AS2 + 4];
                    al[0] = Al32[ra];      al[1] = Al32[ra + 8 * AS2];
                    al[2] = Al32[ra + 4];  al[3] = Al32[ra + 8 * AS2 + 4];
#pragma unroll
                    for (int jl = 0; jl < 10; jl++) {
                        int rb = (8 * jl + gid) * AS2 + ks * 8 + tig;
                        uint32_t bh0 = Bh32[rb], bh1 = Bh32[rb + 4];
                        uint32_t bl0 = Bl32[rb], bl1 = Bl32[rb + 4];
                        float* dd = d[h * 10 + jl];
                        mma16(dd, ah, bh0, bh1);
                        mma16(dd, ah, bl0, bl1);
                        mma16(dd, al, bh0, bh1);
                    }
                }
                __syncthreads();
            }
        }
    }

    // ---------------- epilogue ----------------
#pragma unroll
    for (int half = 0; half < 2; half++) {
        const int r = w * 16 + gid + 8 * half;
        const int p = p0 + r;
        if (MODE == 0) {
            float* zp = zpre + (size_t)p * 160;
#pragma unroll
            for (int g = 0; g < 4; g++)
#pragma unroll
                for (int j = 0; j < 5; j++) {
                    int n = g * 40 + 8 * j + 2 * tig;
                    float2 v = make_float2(d[g * 5 + j][half * 2],
                                           d[g * 5 + j][half * 2 + 1]);
                    *(float2*)(zp + n) = v;
                }
        } else {
            const int b = p / 1600, pp = p - b * 1600;
            const float* zr = zx_t + (size_t)b * zbs + (size_t)pp * 160;
            float* cb = c_buf + (size_t)p * 40;
#pragma unroll
            for (int j = 0; j < 5; j++) {
                const int ch = 8 * j + 2 * tig;
                float2 xi = *(const float2*)(zr + ch);
                float2 xf = *(const float2*)(zr + 40 + ch);
                float2 xg = *(const float2*)(zr + 80 + ch);
                float2 xo = *(const float2*)(zr + 120 + ch);
                float2 cc = *(const float2*)(cb + ch);
                float2 cn, hn, on;
#pragma unroll
                for (int e = 0; e < 2; e++) {
                    int n = ch + e;
                    int di = half * 2 + e;
                    float zi = (e ? xi.y : xi.x) + d[0 * 5 + j][di] + sPar[n];
                    float zf = (e ? xf.y : xf.x) + d[1 * 5 + j][di] + sPar[40 + n];
                    float zg = (e ? xg.y : xg.x) + d[2 * 5 + j][di] + sPar[80 + n];
                    float zo = (e ? xo.y : xo.x) + d[3 * 5 + j][di] + sPar[120 + n];
                    float cold = e ? cc.y : cc.x;
                    float cq = hsig(zf) * cold + hsig(zi) * tanhf(zg);
                    float hq = hsig(zo) * tanhf(cq);
                    float oq = hq * sPar[160 + n] + sPar[200 + n];
                    if (e) { cn.y = cq; hn.y = hq; on.y = oq; }
                    else   { cn.x = cq; hn.x = hq; on.x = oq; }
                }
                *(float2*)(cb + ch) = cn;
                // h stored split (consumed as mma A operand next step)
                uint32_t hw, lw;
                split2(hn, hw, lw);
                *(uint32_t*)(hh_next + (size_t)p * 40 + ch) = hw;
                *(uint32_t*)(hl_next + (size_t)p * 40 + ch) = lw;
                if (MODE == 1) {
                    uint32_t ow, olw;
                    split2(on, ow, olw);
                    *(uint32_t*)(out_h + (size_t)b * bso + (size_t)pp * 40 + ch) = ow;
                    *(uint32_t*)(out_l + (size_t)b * bso + (size_t)pp * 40 + ch) = olw;
                } else {
                    *(float2*)(out_f + (size_t)b * bso + (size_t)pp * 40 + ch) = on;
                }
            }
        }
    }
}

// ---------------- final Conv3D (3x3x3 over T,H,W) + sigmoid ----------------
__global__ __launch_bounds__(320)
void conv3d_kernel(const float* __restrict__ in,    // [B][T][H][W][FF]
                   const float* __restrict__ W3,    // [3][3][3][FF]
                   const float* __restrict__ b3,
                   float* __restrict__ out)         // [B][T][H][W]
{
    __shared__ __align__(16) float ws[27 * FF];
    int tid = threadIdx.y * 40 + threadIdx.x;
    for (int i = tid; i < 27 * FF; i += 320) ws[i] = W3[i];
    __syncthreads();

    const int w   = threadIdx.x;
    const int t   = blockIdx.x * 8 + threadIdx.y;
    const int row = blockIdx.y;
    const int b   = blockIdx.z;

    float acc = b3[0];
#pragma unroll
    for (int dt = 0; dt < 3; dt++) {
        int tt = t + dt - 1;
        if ((unsigned)tt >= NT) continue;
#pragma unroll
        for (int dh = 0; dh < 3; dh++) {
            int rr = row + dh - 1;
            if ((unsigned)rr >= HH) continue;
            const float* rp = in + ((size_t)(b * NT + tt) * HH + rr) * WW * FF;
#pragma unroll
            for (int dw = 0; dw < 3; dw++) {
                int cc = w + dw - 1;
                if ((unsigned)cc >= WW) continue;
                const float4* pp = (const float4*)(rp + (size_t)cc * FF);
                const float*  wp = ws + ((dt * 3 + dh) * 3 + dw) * FF;
#pragma unroll
                for (int q = 0; q < 10; q++) {
                    float4 v  = pp[q];
                    float4 wv = *(const float4*)(wp + q * 4);
                    acc += v.x * wv.x + v.y * wv.y + v.z * wv.z + v.w * wv.w;
                }
            }
        }
    }
    out[((size_t)(b * NT + t) * HH + row) * WW + w] = 1.f / (1.f + expf(-acc));
}

// ---------------- launch ----------------
extern "C" void kernel_launch(void* const* d_in, const int* in_sizes, int n_in,
                              void* d_out, int out_size)
{
    (void)in_sizes; (void)n_in; (void)out_size;
    const float* inputs = (const float*)d_in[0];

    struct LayerP { const float *Wx, *Wh, *b, *g, *be, *mu, *v; };
    LayerP L[4];
    for (int l = 0; l < 4; l++) {
        int base = 1 + 7 * l;
        L[l].Wx = (const float*)d_in[base + 0];
        L[l].Wh = (const float*)d_in[base + 1];
        L[l].b  = (const float*)d_in[base + 2];
        L[l].g  = (const float*)d_in[base + 3];
        L[l].be = (const float*)d_in[base + 4];
        L[l].mu = (const float*)d_in[base + 5];
        L[l].v  = (const float*)d_in[base + 6];
    }
    const float* W3 = (const float*)d_in[29];
    const float* b3 = (const float*)d_in[30];

    float *seqA, *zx, *cbuf;
    bf16 *sqh, *sql, *hA2, *hB2, *Bxh, *Bxl, *Bhh, *Bhl;
    cudaGetSymbolAddress((void**)&seqA, g_seqA);
    cudaGetSymbolAddress((void**)&zx,   g_zx);
    cudaGetSymbolAddress((void**)&sqh,  g_sqh);
    cudaGetSymbolAddress((void**)&sql,  g_sql);
    cudaGetSymbolAddress((void**)&hA2,  g_hA2);
    cudaGetSymbolAddress((void**)&hB2,  g_hB2);
    cudaGetSymbolAddress((void**)&cbuf, g_c);
    cudaGetSymbolAddress((void**)&Bxh,  g_Bxh);
    cudaGetSymbolAddress((void**)&Bxl,  g_Bxl);
    cudaGetSymbolAddress((void**)&Bhh,  g_Bhh);
    cudaGetSymbolAddress((void**)&Bhl,  g_Bhl);

    // smem (bytes)
    const int SM1  = (64 * 24 * 2 + 160 * 24 * 2) * 2 + 240 * 4;   // 22464
    const int SM40 = (64 * 88 * 2 + 80 * 88 * 2) * 2 + 240 * 4;    // 51648
    cudaFuncSetAttribute(mma_step<1, 0>,  cudaFuncAttributeMaxDynamicSharedMemorySize, SM1);
    cudaFuncSetAttribute(mma_step<40, 0>, cudaFuncAttributeMaxDynamicSharedMemorySize, SM40);
    cudaFuncSetAttribute(mma_step<40, 1>, cudaFuncAttributeMaxDynamicSharedMemorySize, SM40);
    cudaFuncSetAttribute(mma_step<40, 2>, cudaFuncAttributeMaxDynamicSharedMemorySize, SM40);

    const int NHC = NB * HH * WW * FF;                   // 1,024,000
    const long long ZBS = (long long)NT * 1600 * 160;    // z per-b stride
    const long long BSO = (long long)NT * 1600 * 40;     // seq per-b stride

    for (int l = 0; l < 4; l++) {
        // zeros first (keeps REC at launch index 5 in layer 0 for ncu)
        zero_kernel<<<(NHC + 255) / 256, 256>>>((float*)hA2, NHC);  // 2M bf16 = 1M floats
        zero_kernel<<<(NHC + 255) / 256, 256>>>(cbuf, NHC);

        const int mode = l ? 1 : 0;
        const int nbx  = l ? BPK : (160 * 16);
        build_B_kernel<<<(nbx + 255) / 256, 256>>>(L[l].Wx, mode, Bxh, Bxl);
        build_B_kernel<<<(BPK + 255) / 256, 256>>>(L[l].Wh, 1, Bhh, Bhl);

        // ---- PRE: x-conv for all (b,t), M = 819200 rows
        if (l == 0)
            mma_step<1, 0><<<12800, 128, SM1>>>(inputs, nullptr, nullptr, 1600,
                Bxh, Bxl, zx, nullptr, 0,
                nullptr, nullptr, nullptr, nullptr, nullptr,
                nullptr, nullptr, nullptr, nullptr, nullptr, nullptr, 0);
        else
            mma_step<40, 0><<<12800, 128, SM40>>>(nullptr, sqh, sql, 64000,
                Bxh, Bxl, zx, nullptr, 0,
                nullptr, nullptr, nullptr, nullptr, nullptr,
                nullptr, nullptr, nullptr, nullptr, nullptr, nullptr, 0);

        // ---- REC: 32 sequential steps
        bf16* hc = hA2;
        bf16* hn = hB2;
        const size_t HN = (size_t)NB * HH * WW * FF;
        for (int t = 0; t < NT; t++) {
            if (l < 3)
                mma_step<40, 1><<<400, 128, SM40>>>(nullptr, hc, hc + HN, 64000,
                    Bhh, Bhl, nullptr, zx + (size_t)t * 1600 * 160, ZBS,
                    L[l].b, L[l].g, L[l].be, L[l].mu, L[l].v,
                    hn, hn + HN, cbuf,
                    nullptr, sqh + (size_t)t * 1600 * 40, sql + (size_t)t * 1600 * 40, BSO);
            else
                mma_step<40, 2><<<400, 128, SM40>>>(nullptr, hc, hc + HN, 64000,
                    Bhh, Bhl, nullptr, zx + (size_t)t * 1600 * 160, ZBS,
                    L[l].b, L[l].g, L[l].be, L[l].mu, L[l].v,
                    hn, hn + HN, cbuf,
                    seqA + (size_t)t * 1600 * 40, nullptr, nullptr, BSO);
            bf16* tmp = hc; hc = hn; hn = tmp;
        }
    }

    conv3d_kernel<<<dim3(4, HH, NB), dim3(40, 8)>>>(seqA, W3, b3, (float*)d_out);
}

// round 16
// speedup vs baseline: 1.3366x; 1.3366x over previous
#include <cuda_runtime.h>
#include <cuda_bf16.h>
#include <math.h>
#include <stdint.h>

#define NB 16
#define NT 32
#define HH 40
#define WW 40
#define FF 40

typedef __nv_bfloat16 bf16;

// ---------------- scratch (no allocations allowed) ----------------
__device__ float g_seqA[(size_t)NB*NT*HH*WW*FF];      // 131 MB (layer-3 fp32 out)
__device__ float g_zx [(size_t)NB*NT*HH*WW*160];      // 524 MB x-conv precompute
__device__ bf16  g_sqh[(size_t)NB*NT*HH*WW*FF];       // inter-layer out split hi
__device__ bf16  g_sql[(size_t)NB*NT*HH*WW*FF];       // inter-layer out split lo
__device__ bf16  g_hA2[2*(size_t)NB*HH*WW*FF];        // h ping: [hi | lo]
__device__ bf16  g_hB2[2*(size_t)NB*HH*WW*FF];        // h pong: [hi | lo]
__device__ float g_c  [NB*HH*WW*FF];
__device__ bf16 g_Bxh[9*160*48], g_Bxl[9*160*48];     // weights [c][n][48] hi/lo
__device__ bf16 g_Bhh[9*160*48], g_Bhl[9*160*48];

__global__ void zero_kernel(float* __restrict__ p, int n) {
    int i = blockIdx.x * blockDim.x + threadIdx.x;
    if (i < n) p[i] = 0.f;
}

__device__ __forceinline__ float hsig(float x) {
    return fminf(fmaxf(0.2f * x + 0.5f, 0.f), 1.f);
}
__device__ __forceinline__ void mma16(float* d, const uint32_t* a, uint32_t b0, uint32_t b1) {
    asm volatile("mma.sync.aligned.m16n8k16.row.col.f32.bf16.bf16.f32 "
        "{%0,%1,%2,%3}, {%4,%5,%6,%7}, {%8,%9}, {%0,%1,%2,%3};"
        : "+f"(d[0]), "+f"(d[1]), "+f"(d[2]), "+f"(d[3])
        : "r"(a[0]), "r"(a[1]), "r"(a[2]), "r"(a[3]), "r"(b0), "r"(b1));
}
__device__ __forceinline__ void split_bf16(float v, bf16& hi, bf16& lo) {
    hi = __float2bfloat16_rn(v);
    lo = __float2bfloat16_rn(v - __bfloat162float(hi));
}
__device__ __forceinline__ void split2(float2 v, uint32_t& hw, uint32_t& lw) {
    __nv_bfloat162 H, L;
    split_bf16(v.x, H.x, L.x);
    split_bf16(v.y, H.y, L.y);
    hw = *(uint32_t*)&H;
    lw = *(uint32_t*)&L;
}

// ---- weight prepass ----
// mode 0 (CIN=1):  [n][16]:    k<9 -> W[k*160+n], else 0        (160*16)
// mode 1 (CIN=40): [c][n][48]: j<40 -> W[(c*40+j)*160+n], else 0 (9*160*48)
__global__ void build_B_kernel(const float* __restrict__ W, int mode,
                               bf16* __restrict__ Bh, bf16* __restrict__ Bl)
{
    int idx = blockIdx.x * blockDim.x + threadIdx.x;
    float v = 0.f;
    if (mode == 0) {
        if (idx >= 160 * 16) return;
        int n = idx / 16, k = idx & 15;
        if (k < 9) v = W[k * 160 + n];
    } else {
        if (idx >= 9 * 160 * 48) return;
        int c = idx / 7680, r = idx - c * 7680;
        int n = r / 48, j = r - n * 48;
        if (j < 40) v = W[(size_t)(c * 40 + j) * 160 + n];
    }
    bf16 hi, lo;
    split_bf16(v, hi, lo);
    Bh[idx] = hi;
    Bl[idx] = lo;
}

// ---------------- GEMM step via mma.sync bf16 (3-term hi/lo split) --------
// z[M,160] = im2col(X)[M, K=9*CIN] @ B[160,K]^T
// 9 chunks of 48k (8 pad), full 160-row B per chunk (R14 structure).
// MODE 0: PRE (z fp32). MODE 1: REC, split-bf16 out. MODE 2: REC, fp32 out.
// MROWS: 64 (REC, 128 thr) or 128 (PRE, 256 thr).
template<int CIN, int MODE, int MROWS>
__global__ __launch_bounds__(MROWS * 2, (MROWS == 64) ? 3 : 2)
void mma_step(const float* __restrict__ Xf,                              // CIN=1 src
              const bf16* __restrict__ Xh, const bf16* __restrict__ Xl,  // CIN=40 src (pre-split)
              long long xbs,
              const bf16* __restrict__ Bh_g, const bf16* __restrict__ Bl_g,
              float* __restrict__ zpre,
              const float* __restrict__ zx_t, long long zbs,
              const float* __restrict__ bias,
              const float* __restrict__ gam, const float* __restrict__ bet,
              const float* __restrict__ mu, const float* __restrict__ var,
              bf16* __restrict__ hh_next, bf16* __restrict__ hl_next,
              float* __restrict__ c_buf,
              float* __restrict__ out_f,
              bf16* __restrict__ out_h, bf16* __restrict__ out_l,
              long long bso)
{
    constexpr int ASTR = (CIN == 1) ? 24 : 56;     // bf16 row stride
    constexpr int AS2  = ASTR / 2;                 // b32 row stride
    constexpr int NTH  = MROWS * 2;

    extern __shared__ char smem[];
    bf16* sAh = (bf16*)smem;
    bf16* sAl = sAh + MROWS * ASTR;
    bf16* sBh = sAl + MROWS * ASTR;
    bf16* sBl = sBh + 160 * ASTR;
    float* sPar = (float*)(sBl + 160 * ASTR);      // bias[160], scale[40], shift[40]

    const int tid = threadIdx.x;
    const int w   = tid >> 5;
    const int lane = tid & 31;
    const int gid = lane >> 2;
    const int tig = lane & 3;
    const int p0  = blockIdx.x * MROWS;

    if (MODE != 0) {
        for (int i = tid; i < 240; i += NTH) {
            if (i < 160) sPar[i] = bias[i];
            else if (i < 200) {
                int f = i - 160;
                sPar[i] = gam[f] * rsqrtf(var[f] + 1e-3f);
            } else {
                int f = i - 200;
                sPar[i] = bet[f] - mu[f] * (gam[f] * rsqrtf(var[f] + 1e-3f));
            }
        }
    }

    float d[20][4];
#pragma unroll
    for (int j = 0; j < 20; j++)
#pragma unroll
        for (int e = 0; e < 4; e++) d[j][e] = 0.f;

    if (CIN == 1) {
        // ---------------- layer-0 PRE path (K=9 -> 16) ----------------
        for (int i = tid; i < MROWS; i += NTH) {
            int p = p0 + i;
            int unit = p / 1600, pp = p - unit * 1600;
            int pr = pp / 40, pw = pp - pr * 40;
            bf16* ph = sAh + i * ASTR;
            bf16* pl = sAl + i * ASTR;
#pragma unroll
            for (int k = 0; k < 16; k += 2) {
                float v0 = 0.f, v1 = 0.f;
                if (k < 9) {
                    int rr = pr + k / 3 - 1, cc = pw + k % 3 - 1;
                    if ((unsigned)rr < 40u && (unsigned)cc < 40u)
                        v0 = Xf[(size_t)unit * xbs + rr * 40 + cc];
                }
                if (k + 1 < 9) {
                    int k1 = k + 1;
                    int rr = pr + k1 / 3 - 1, cc = pw + k1 % 3 - 1;
                    if ((unsigned)rr < 40u && (unsigned)cc < 40u)
                        v1 = Xf[(size_t)unit * xbs + rr * 40 + cc];
                }
                __nv_bfloat162 h2, l2;
                split_bf16(v0, h2.x, l2.x);
                split_bf16(v1, h2.y, l2.y);
                *(__nv_bfloat162*)(ph + k) = h2;
                *(__nv_bfloat162*)(pl + k) = l2;
            }
        }
        for (int i = tid; i < 320; i += NTH) {
            int n = i >> 1, g = i & 1;
            *(float4*)(sBh + n * ASTR + g * 8) = *(const float4*)(Bh_g + n * 16 + g * 8);
            *(float4*)(sBl + n * ASTR + g * 8) = *(const float4*)(Bl_g + n * 16 + g * 8);
        }
        __syncthreads();

        const uint32_t* Ah32 = (const uint32_t*)sAh;
        const uint32_t* Al32 = (const uint32_t*)sAl;
        const uint32_t* Bh32 = (const uint32_t*)sBh;
        const uint32_t* Bl32 = (const uint32_t*)sBl;
        uint32_t ah[4], al[4];
        {
            int ra = (w * 16 + gid) * AS2 + tig;
            ah[0] = Ah32[ra];      ah[1] = Ah32[ra + 8 * AS2];
            ah[2] = Ah32[ra + 4];  ah[3] = Ah32[ra + 8 * AS2 + 4];
            al[0] = Al32[ra];      al[1] = Al32[ra + 8 * AS2];
            al[2] = Al32[ra + 4];  al[3] = Al32[ra + 8 * AS2 + 4];
        }
#pragma unroll
        for (int j = 0; j < 20; j++) {
            int rb = (8 * j + gid) * AS2 + tig;
            uint32_t bh0 = Bh32[rb], bh1 = Bh32[rb + 4];
            uint32_t bl0 = Bl32[rb], bl1 = Bl32[rb + 4];
            mma16(d[j], ah, bh0, bh1);
            mma16(d[j], ah, bl0, bl1);
            mma16(d[j], al, bh0, bh1);
        }
        __syncthreads();
    } else {
        // ---------------- CIN=40: 9 chunks of 48k (8 pad) ----------------
        // pre-zero A pad cols 40..47 once (never rewritten)
        for (int r = tid; r < MROWS; r += NTH) {
            *(float4*)(sAh + r * ASTR + 40) = make_float4(0.f, 0.f, 0.f, 0.f);
            *(float4*)(sAl + r * ASTR + 40) = make_float4(0.f, 0.f, 0.f, 0.f);
        }

#pragma unroll 1
        for (int c = 0; c < 9; c++) {
            const int dyy = c / 3 - 1, dxx = c % 3 - 1;
            // ---- stage A: pre-split bf16, 16B units, halo zero-fill
            for (int i = tid; i < MROWS * 5; i += NTH) {
                int row = i / 5, slot = i - (i / 5) * 5;
                int p = p0 + row;
                int unit = p / 1600, pp = p - unit * 1600;
                int pr = pp / 40, pw = pp - pr * 40;
                int rr = pr + dyy, cc = pw + dxx;
                uint4 vh = make_uint4(0, 0, 0, 0), vl = vh;
                if ((unsigned)rr < 40u && (unsigned)cc < 40u) {
                    size_t src = (size_t)unit * xbs + (size_t)(rr * 40 + cc) * 40 + slot * 8;
                    vh = *(const uint4*)(Xh + src);
                    vl = *(const uint4*)(Xl + src);
                }
                *(uint4*)(sAh + row * ASTR + slot * 8) = vh;
                *(uint4*)(sAl + row * ASTR + slot * 8) = vl;
            }
            // ---- stage B: [c][n][48] pre-split
            for (int i = tid; i < 960; i += NTH) {
                int n = i / 6, s = i - (i / 6) * 6;
                size_t src = (size_t)(c * 160 + n) * 48 + s * 8;
                *(uint4*)(sBh + n * ASTR + s * 8) = *(const uint4*)(Bh_g + src);
                *(uint4*)(sBl + n * ASTR + s * 8) = *(const uint4*)(Bl_g + src);
            }
            __syncthreads();

            const uint32_t* Ah32 = (const uint32_t*)sAh;
            const uint32_t* Al32 = (const uint32_t*)sAl;
            const uint32_t* Bh32 = (const uint32_t*)sBh;
            const uint32_t* Bl32 = (const uint32_t*)sBl;
#pragma unroll
            for (int ks = 0; ks < 3; ks++) {
                uint32_t ah[4], al[4];
                int ra = (w * 16 + gid) * AS2 + ks * 8 + tig;
                ah[0] = Ah32[ra];      ah[1] = Ah32[ra + 8 * AS2];
                ah[2] = Ah32[ra + 4];  ah[3] = Ah32[ra + 8 * AS2 + 4];
                al[0] = Al32[ra];      al[1] = Al32[ra + 8 * AS2];
                al[2] = Al32[ra + 4];  al[3] = Al32[ra + 8 * AS2 + 4];
#pragma unroll
                for (int j = 0; j < 20; j++) {
                    int rb = (8 * j + gid) * AS2 + ks * 8 + tig;
                    uint32_t bh0 = Bh32[rb], bh1 = Bh32[rb + 4];
                    uint32_t bl0 = Bl32[rb], bl1 = Bl32[rb + 4];
                    mma16(d[j], ah, bh0, bh1);
                    mma16(d[j], ah, bl0, bl1);
                    mma16(d[j], al, bh0, bh1);
                }
            }
            __syncthreads();
        }
    }

    // ---------------- epilogue ----------------
#pragma unroll
    for (int half = 0; half < 2; half++) {
        const int r = w * 16 + gid + 8 * half;
        const int p = p0 + r;
        if (MODE == 0) {
            float* zp = zpre + (size_t)p * 160;
#pragma unroll
            for (int g = 0; g < 4; g++)
#pragma unroll
                for (int j = 0; j < 5; j++) {
                    int n = g * 40 + 8 * j + 2 * tig;
                    float2 v = make_float2(d[g * 5 + j][half * 2],
                                           d[g * 5 + j][half * 2 + 1]);
                    *(float2*)(zp + n) = v;
                }
        } else {
            const int b = p / 1600, pp = p - b * 1600;
            const float* zr = zx_t + (size_t)b * zbs + (size_t)pp * 160;
            float* cb = c_buf + (size_t)p * 40;
#pragma unroll
            for (int j = 0; j < 5; j++) {
                const int ch = 8 * j + 2 * tig;
                float2 xi = *(const float2*)(zr + ch);
                float2 xf = *(const float2*)(zr + 40 + ch);
                float2 xg = *(const float2*)(zr + 80 + ch);
                float2 xo = *(const float2*)(zr + 120 + ch);
                float2 cc = *(const float2*)(cb + ch);
                float2 cn, hn, on;
#pragma unroll
                for (int e = 0; e < 2; e++) {
                    int n = ch + e;
                    int di = half * 2 + e;
                    float zi = (e ? xi.y : xi.x) + d[0 * 5 + j][di] + sPar[n];
                    float zf = (e ? xf.y : xf.x) + d[1 * 5 + j][di] + sPar[40 + n];
                    float zg = (e ? xg.y : xg.x) + d[2 * 5 + j][di] + sPar[80 + n];
                    float zo = (e ? xo.y : xo.x) + d[3 * 5 + j][di] + sPar[120 + n];
                    float cold = e ? cc.y : cc.x;
                    float cq = hsig(zf) * cold + hsig(zi) * tanhf(zg);
                    float hq = hsig(zo) * tanhf(cq);
                    float oq = hq * sPar[160 + n] + sPar[200 + n];
                    if (e) { cn.y = cq; hn.y = hq; on.y = oq; }
                    else   { cn.x = cq; hn.x = hq; on.x = oq; }
                }
                *(float2*)(cb + ch) = cn;
                uint32_t hw, lw;
                split2(hn, hw, lw);
                *(uint32_t*)(hh_next + (size_t)p * 40 + ch) = hw;
                *(uint32_t*)(hl_next + (size_t)p * 40 + ch) = lw;
                if (MODE == 1) {
                    uint32_t ow, olw;
                    split2(on, ow, olw);
                    *(uint32_t*)(out_h + (size_t)b * bso + (size_t)pp * 40 + ch) = ow;
                    *(uint32_t*)(out_l + (size_t)b * bso + (size_t)pp * 40 + ch) = olw;
                } else {
                    *(float2*)(out_f + (size_t)b * bso + (size_t)pp * 40 + ch) = on;
                }
            }
        }
    }
}

// ---------------- final Conv3D (3x3x3 over T,H,W) + sigmoid ----------------
__global__ __launch_bounds__(320)
void conv3d_kernel(const float* __restrict__ in,    // [B][T][H][W][FF]
                   const float* __restrict__ W3,    // [3][3][3][FF]
                   const float* __restrict__ b3,
                   float* __restrict__ out)         // [B][T][H][W]
{
    __shared__ __align__(16) float ws[27 * FF];
    int tid = threadIdx.y * 40 + threadIdx.x;
    for (int i = tid; i < 27 * FF; i += 320) ws[i] = W3[i];
    __syncthreads();

    const int w   = threadIdx.x;
    const int t   = blockIdx.x * 8 + threadIdx.y;
    const int row = blockIdx.y;
    const int b   = blockIdx.z;

    float acc = b3[0];
#pragma unroll
    for (int dt = 0; dt < 3; dt++) {
        int tt = t + dt - 1;
        if ((unsigned)tt >= NT) continue;
#pragma unroll
        for (int dh = 0; dh < 3; dh++) {
            int rr = row + dh - 1;
            if ((unsigned)rr >= HH) continue;
            const float* rp = in + ((size_t)(b * NT + tt) * HH + rr) * WW * FF;
#pragma unroll
            for (int dw = 0; dw < 3; dw++) {
                int cc = w + dw - 1;
                if ((unsigned)cc >= WW) continue;
                const float4* pp = (const float4*)(rp + (size_t)cc * FF);
                const float*  wp = ws + ((dt * 3 + dh) * 3 + dw) * FF;
#pragma unroll
                for (int q = 0; q < 10; q++) {
                    float4 v  = pp[q];
                    float4 wv = *(const float4*)(wp + q * 4);
                    acc += v.x * wv.x + v.y * wv.y + v.z * wv.z + v.w * wv.w;
                }
            }
        }
    }
    out[((size_t)(b * NT + t) * HH + row) * WW + w] = 1.f / (1.f + expf(-acc));
}

// ---------------- launch ----------------
extern "C" void kernel_launch(void* const* d_in, const int* in_sizes, int n_in,
                              void* d_out, int out_size)
{
    (void)in_sizes; (void)n_in; (void)out_size;
    const float* inputs = (const float*)d_in[0];

    struct LayerP { const float *Wx, *Wh, *b, *g, *be, *mu, *v; };
    LayerP L[4];
    for (int l = 0; l < 4; l++) {
        int base = 1 + 7 * l;
        L[l].Wx = (const float*)d_in[base + 0];
        L[l].Wh = (const float*)d_in[base + 1];
        L[l].b  = (const float*)d_in[base + 2];
        L[l].g  = (const float*)d_in[base + 3];
        L[l].be = (const float*)d_in[base + 4];
        L[l].mu = (const float*)d_in[base + 5];
        L[l].v  = (const float*)d_in[base + 6];
    }
    const float* W3 = (const float*)d_in[29];
    const float* b3 = (const float*)d_in[30];

    float *seqA, *zx, *cbuf;
    bf16 *sqh, *sql, *hA2, *hB2, *Bxh, *Bxl, *Bhh, *Bhl;
    cudaGetSymbolAddress((void**)&seqA, g_seqA);
    cudaGetSymbolAddress((void**)&zx,   g_zx);
    cudaGetSymbolAddress((void**)&sqh,  g_sqh);
    cudaGetSymbolAddress((void**)&sql,  g_sql);
    cudaGetSymbolAddress((void**)&hA2,  g_hA2);
    cudaGetSymbolAddress((void**)&hB2,  g_hB2);
    cudaGetSymbolAddress((void**)&cbuf, g_c);
    cudaGetSymbolAddress((void**)&Bxh,  g_Bxh);
    cudaGetSymbolAddress((void**)&Bxl,  g_Bxl);
    cudaGetSymbolAddress((void**)&Bhh,  g_Bhh);
    cudaGetSymbolAddress((void**)&Bhl,  g_Bhl);

    // smem (bytes)
    const int SM1_128  = (128 * 24 * 2 + 160 * 24 * 2) * 2 + 960;   // 28608
    const int SM40_128 = (128 * 56 * 2 + 160 * 56 * 2) * 2 + 960;   // 65472
    const int SM40_64  = (64 * 56 * 2 + 160 * 56 * 2) * 2 + 960;    // 51136
    cudaFuncSetAttribute(mma_step<1, 0, 128>,  cudaFuncAttributeMaxDynamicSharedMemorySize, SM1_128);
    cudaFuncSetAttribute(mma_step<40, 0, 128>, cudaFuncAttributeMaxDynamicSharedMemorySize, SM40_128);
    cudaFuncSetAttribute(mma_step<40, 1, 64>,  cudaFuncAttributeMaxDynamicSharedMemorySize, SM40_64);
    cudaFuncSetAttribute(mma_step<40, 2, 64>,  cudaFuncAttributeMaxDynamicSharedMemorySize, SM40_64);

    const int NHC = NB * HH * WW * FF;                   // 1,024,000
    const long long ZBS = (long long)NT * 1600 * 160;    // z per-b stride
    const long long BSO = (long long)NT * 1600 * 40;     // seq per-b stride

    for (int l = 0; l < 4; l++) {
        zero_kernel<<<(NHC + 255) / 256, 256>>>((float*)hA2, NHC);  // 2M bf16
        zero_kernel<<<(NHC + 255) / 256, 256>>>(cbuf, NHC);

        const int mode = l ? 1 : 0;
        const int nbx  = l ? (9 * 160 * 48) : (160 * 16);
        build_B_kernel<<<(nbx + 255) / 256, 256>>>(L[l].Wx, mode, Bxh, Bxl);
        build_B_kernel<<<(9 * 160 * 48 + 255) / 256, 256>>>(L[l].Wh, 1, Bhh, Bhl);

        // ---- PRE: x-conv for all (b,t), M = 819200 rows, 128/CTA
        if (l == 0)
            mma_step<1, 0, 128><<<6400, 256, SM1_128>>>(inputs, nullptr, nullptr, 1600,
                Bxh, Bxl, zx, nullptr, 0,
                nullptr, nullptr, nullptr, nullptr, nullptr,
                nullptr, nullptr, nullptr, nullptr, nullptr, nullptr, 0);
        else
            mma_step<40, 0, 128><<<6400, 256, SM40_128>>>(nullptr, sqh, sql, 64000,
                Bxh, Bxl, zx, nullptr, 0,
                nullptr, nullptr, nullptr, nullptr, nullptr,
                nullptr, nullptr, nullptr, nullptr, nullptr, nullptr, 0);

        // ---- REC: 32 sequential steps, 64 rows/CTA (400 CTAs, one wave)
        bf16* hc = hA2;
        bf16* hn = hB2;
        const size_t HN = (size_t)NB * HH * WW * FF;
        for (int t = 0; t < NT; t++) {
            if (l < 3)
                mma_step<40, 1, 64><<<400, 128, SM40_64>>>(nullptr, hc, hc + HN, 64000,
                    Bhh, Bhl, nullptr, zx + (size_t)t * 1600 * 160, ZBS,
                    L[l].b, L[l].g, L[l].be, L[l].mu, L[l].v,
                    hn, hn + HN, cbuf,
                    nullptr, sqh + (size_t)t * 1600 * 40, sql + (size_t)t * 1600 * 40, BSO);
            else
                mma_step<40, 2, 64><<<400, 128, SM40_64>>>(nullptr, hc, hc + HN, 64000,
                    Bhh, Bhl, nullptr, zx + (size_t)t * 1600 * 160, ZBS,
                    L[l].b, L[l].g, L[l].be, L[l].mu, L[l].v,
                    hn, hn + HN, cbuf,
                    seqA + (size_t)t * 1600 * 40, nullptr, nullptr, BSO);
            bf16* tmp = hc; hc = hn; hn = tmp;
        }
    }

    conv3d_kernel<<<dim3(4, HH, NB), dim3(40, 8)>>>(seqA, W3, b3, (float*)d_out);
}